// round 3
// baseline (speedup 1.0000x reference)
#include <cuda_runtime.h>
#include <cuda_bf16.h>
#include <cstdint>

// ============================================================================
// sim = clamp(xn @ xn.T, 0), xn = row-normalized features (8192 x 256 fp32)
//
// sm_100 (NO 'a' suffix -> no tcgen05). Use arch-portable tensor path:
//   mma.sync.aligned.m16n8k16 bf16 + cp.async + ldmatrix.
//
// Accuracy: bf16 split x = hi + lo, symmetric-operand K-tripling:
//   A rows = [hi | lo | hi], B rows = [hi | hi | lo]  (virtual K = 768)
//   => C = hi.hi^T + lo.hi^T + hi.lo^T   (drops lo.lo^T ~ 1e-7)
//
// Symmetry: compute only lower-triangle tiles (by >= bx), mirror via smem
// transpose. 2080 tiles instead of 4096.
// ============================================================================

#define NROWS  8192
#define DIM    256
#define TILE   128
#define KCH    64           // bf16 per K-chunk (128 B rows)
#define NCHUNK 12           // virtual K = 768

// Split buffer: per row, cols [0,256)=hi, [256,512)=lo.  8 MB scratch.
__device__ __align__(128) __nv_bfloat16 g_X[(size_t)NROWS * 512];

// ---------------------------------------------------------------------------
__device__ __forceinline__ uint32_t smem_u32(const void* p) {
    uint32_t a;
    asm("{ .reg .u64 t; cvta.to.shared.u64 t, %1; cvt.u32.u64 %0, t; }"
        : "=r"(a) : "l"(p));
    return a;
}

#define CP_ASYNC_16(dst, src) \
    asm volatile("cp.async.cg.shared.global [%0], [%1], 16;" \
                 :: "r"(dst), "l"(src) : "memory")
#define CP_ASYNC_COMMIT() \
    asm volatile("cp.async.commit_group;" ::: "memory")
#define CP_ASYNC_WAIT(n) \
    asm volatile("cp.async.wait_group %0;" :: "n"(n) : "memory")

__device__ __forceinline__ void ldsm4(uint32_t* r, uint32_t addr) {
    asm volatile("ldmatrix.sync.aligned.m8n8.x4.shared.b16 {%0,%1,%2,%3}, [%4];"
                 : "=r"(r[0]), "=r"(r[1]), "=r"(r[2]), "=r"(r[3]) : "r"(addr));
}

__device__ __forceinline__ void mma16816(float* d, const uint32_t* a,
                                         const uint32_t* b) {
    asm volatile(
        "mma.sync.aligned.m16n8k16.row.col.f32.bf16.bf16.f32 "
        "{%0,%1,%2,%3}, {%4,%5,%6,%7}, {%8,%9}, {%0,%1,%2,%3};"
        : "+f"(d[0]), "+f"(d[1]), "+f"(d[2]), "+f"(d[3])
        : "r"(a[0]), "r"(a[1]), "r"(a[2]), "r"(a[3]), "r"(b[0]), "r"(b[1]));
}

// ---------------------------------------------------------------------------
// Kernel 1: normalize rows, emit bf16 split [hi | lo].
// One warp per row; 256 threads -> 8 rows / block.
// ---------------------------------------------------------------------------
__global__ void __launch_bounds__(256)
norm_split_kernel(const float* __restrict__ feats)
{
    const int row  = blockIdx.x * 8 + (threadIdx.x >> 5);
    const int lane = threadIdx.x & 31;

    const float4* src = reinterpret_cast<const float4*>(feats + (size_t)row * DIM);
    float4 v0 = src[lane * 2];
    float4 v1 = src[lane * 2 + 1];

    float ss = v0.x * v0.x + v0.y * v0.y + v0.z * v0.z + v0.w * v0.w
             + v1.x * v1.x + v1.y * v1.y + v1.z * v1.z + v1.w * v1.w;
    #pragma unroll
    for (int o = 16; o; o >>= 1)
        ss += __shfl_xor_sync(0xFFFFFFFFu, ss, o);

    const float inv = 1.0f / fmaxf(sqrtf(ss), 1e-8f);

    float vals[8] = {v0.x, v0.y, v0.z, v0.w, v1.x, v1.y, v1.z, v1.w};
    const size_t base = (size_t)row * 512;
    #pragma unroll
    for (int j = 0; j < 8; ++j) {
        const int c = lane * 8 + j;
        float xn = vals[j] * inv;
        __nv_bfloat16 hi = __float2bfloat16(xn);
        __nv_bfloat16 lo = __float2bfloat16(xn - __bfloat162float(hi));
        g_X[base + c]       = hi;
        g_X[base + 256 + c] = lo;
    }
}

// ---------------------------------------------------------------------------
// Kernel 2: bf16 mma.sync GEMM, 128x128 tile, 8 warps (warp tile 64x32),
// 2-stage cp.async double buffer, lower-triangle tiles + mirrored write.
//
// smem: stages:  As [2][128][128B]  at 0      (16 KB * 2)
//               Bs [2][128][128B]  at 32768  (16 KB * 2)
//       ctile:  float[128][129]    at 0      (66048 B, reused after mainloop)
// ---------------------------------------------------------------------------
#define SMEM_STAGE_SZ 16384
#define SMEM_B_OFF    32768
#define SMEM_TOTAL    66048        // max(65536, 128*129*4)

__global__ void __launch_bounds__(256, 2)
cosine_gemm_kernel(float* __restrict__ out)
{
    extern __shared__ char smem[];
    const uint32_t sbase = smem_u32(smem);
    const int tid  = threadIdx.x;
    const int lane = tid & 31;
    const int wid  = tid >> 5;

    // Triangular tile decode: t -> (by, bx), bx <= by
    const int t = blockIdx.x;
    int by = (int)((sqrtf(8.0f * (float)t + 1.0f) - 1.0f) * 0.5f);
    while ((by + 1) * (by + 2) / 2 <= t) ++by;
    while (by * (by + 1) / 2 > t) --by;
    const int bx = t - by * (by + 1) / 2;

    const int rowbase = by * TILE;   // M rows (A operand)
    const int colbase = bx * TILE;   // N cols (B operand)

    const int wm = (wid & 1) * 64;   // warp tile origin in M
    const int wn = (wid >> 1) * 32;  // warp tile origin in N

    // --- cp.async tile loader: 8 x 16B per thread per chunk --------------
    const int lr = tid >> 3;         // 0..31  (row group)
    const int lc = tid & 7;          // 0..7   (16B chunk)

    auto issue = [&](int kc) {
        const int ka = (kc < 8) ? kc : kc - 8;   // A: [hi | lo | hi]
        const int kb = (kc < 4) ? kc : kc - 4;   // B: [hi | hi | lo]
        const uint32_t stg = (uint32_t)(kc & 1) * SMEM_STAGE_SZ;
        #pragma unroll
        for (int p = 0; p < 4; ++p) {
            const int row = p * 32 + lr;
            const uint32_t swc = (uint32_t)((lc ^ (row & 7)) * 16);
            const __nv_bfloat16* sA =
                &g_X[(size_t)(rowbase + row) * 512 + ka * KCH + lc * 8];
            const __nv_bfloat16* sB =
                &g_X[(size_t)(colbase + row) * 512 + kb * KCH + lc * 8];
            CP_ASYNC_16(sbase + stg + row * 128 + swc, sA);
            CP_ASYNC_16(sbase + SMEM_B_OFF + stg + row * 128 + swc, sB);
        }
        CP_ASYNC_COMMIT();
    };

    float acc[4][4][4];
    #pragma unroll
    for (int i = 0; i < 4; ++i)
        #pragma unroll
        for (int j = 0; j < 4; ++j)
            #pragma unroll
            for (int r = 0; r < 4; ++r)
                acc[i][j][r] = 0.0f;

    issue(0);
    issue(1);

    for (int kc = 0; kc < NCHUNK; ++kc) {
        if (kc == NCHUNK - 1) { CP_ASYNC_WAIT(0); } else { CP_ASYNC_WAIT(1); }
        __syncthreads();

        const uint32_t stg = (uint32_t)(kc & 1) * SMEM_STAGE_SZ;
        const uint32_t aB = sbase + stg;
        const uint32_t bB = sbase + SMEM_B_OFF + stg;

        #pragma unroll
        for (int s = 0; s < 4; ++s) {             // 4 x K16 per chunk
            uint32_t afr[4][4];
            #pragma unroll
            for (int i = 0; i < 4; ++i) {
                const int row = wm + 16 * i + (lane & 15);
                const int ch  = s * 2 + (lane >> 4);
                ldsm4(afr[i], aB + row * 128 + ((ch ^ (row & 7)) * 16));
            }
            uint32_t bfr[2][4];
            #pragma unroll
            for (int jj = 0; jj < 2; ++jj) {
                const int row = wn + 16 * jj + ((lane >> 4) << 3) + (lane & 7);
                const int ch  = s * 2 + ((lane >> 3) & 1);
                ldsm4(bfr[jj], bB + row * 128 + ((ch ^ (row & 7)) * 16));
            }
            #pragma unroll
            for (int i = 0; i < 4; ++i)
                #pragma unroll
                for (int j = 0; j < 4; ++j)
                    mma16816(acc[i][j], afr[i], &bfr[j >> 1][(j & 1) * 2]);
        }
        __syncthreads();
        if (kc + 2 < NCHUNK) issue(kc + 2);
    }

    // --- Epilogue ---------------------------------------------------------
    // Direct write from registers: float2 = one full 32B sector per quad.
    const int grp  = lane >> 2;        // 0..7
    const int t4   = lane & 3;         // 0..3
    #pragma unroll
    for (int i = 0; i < 4; ++i) {
        #pragma unroll
        for (int j = 0; j < 4; ++j) {
            const size_t gr = (size_t)(rowbase + wm + 16 * i + grp);
            const size_t gc = (size_t)(colbase + wn + 8 * j + t4 * 2);
            float2 v01 = make_float2(fmaxf(acc[i][j][0], 0.0f),
                                     fmaxf(acc[i][j][1], 0.0f));
            float2 v23 = make_float2(fmaxf(acc[i][j][2], 0.0f),
                                     fmaxf(acc[i][j][3], 0.0f));
            *reinterpret_cast<float2*>(&out[gr * NROWS + gc]) = v01;
            *reinterpret_cast<float2*>(&out[(gr + 8) * NROWS + gc]) = v23;
        }
    }

    // Mirrored tile via smem transpose (skip on diagonal).
    if (bx != by) {
        float* ctile = reinterpret_cast<float*>(smem);   // [128][129]
        __syncthreads();   // mainloop smem reads are done
        #pragma unroll
        for (int i = 0; i < 4; ++i) {
            #pragma unroll
            for (int j = 0; j < 4; ++j) {
                const int m = wm + 16 * i + grp;
                const int n = wn + 8 * j + t4 * 2;
                ctile[m * 129 + n]           = fmaxf(acc[i][j][0], 0.0f);
                ctile[m * 129 + n + 1]       = fmaxf(acc[i][j][1], 0.0f);
                ctile[(m + 8) * 129 + n]     = fmaxf(acc[i][j][2], 0.0f);
                ctile[(m + 8) * 129 + n + 1] = fmaxf(acc[i][j][3], 0.0f);
            }
        }
        __syncthreads();
        // warp w handles n = w*16 .. w*16+15 ; column reads are conflict-free
        #pragma unroll
        for (int rr = 0; rr < 16; ++rr) {
            const int n = wid * 16 + rr;
            #pragma unroll
            for (int q = 0; q < 4; ++q) {
                const int m = q * 32 + lane;
                out[(size_t)(colbase + n) * NROWS + rowbase + m] =
                    ctile[m * 129 + n];
            }
        }
    }
}

// ---------------------------------------------------------------------------
extern "C" void kernel_launch(void* const* d_in, const int* in_sizes, int n_in,
                              void* d_out, int out_size)
{
    const float* feats = (const float*)d_in[0];
    float* out = (float*)d_out;
    (void)in_sizes; (void)n_in; (void)out_size;

    cudaFuncSetAttribute(cosine_gemm_kernel,
                         cudaFuncAttributeMaxDynamicSharedMemorySize,
                         SMEM_TOTAL);

    norm_split_kernel<<<NROWS / 8, 256>>>(feats);

    const int ntiles = (NROWS / TILE) * (NROWS / TILE + 1) / 2;   // 2080
    cosine_gemm_kernel<<<ntiles, 256, SMEM_TOTAL>>>(out);
}